// round 5
// baseline (speedup 1.0000x reference)
#include <cuda_runtime.h>

#define BATCH 4
#define C1    32
#define C2    64
#define MROWS 512

// Intermediates (no allocation allowed -> __device__ globals)
__device__ float g_z1 [BATCH * C1 * 256];        // conv1 out: [b][ic][16x16]
__device__ float g_z2t[BATCH * 64 * C2];         // conv2 out, token-major: [b][pix][oc]
__device__ __align__(16) float g_V [MROWS * C2]; // lookup @ Wv        [m][d]
__device__ float g_LT[C2 * MROWS];               // lookup transposed  [k][m]

// ---------------------------------------------------------------------------
// K1: blocks [0,128) conv1; blocks [128,256) vmat + lookup transpose.
// ---------------------------------------------------------------------------
__global__ void __launch_bounds__(256) k1_kernel(
    const float* __restrict__ x,  const float* __restrict__ w1,
    const float* __restrict__ b1, const float* __restrict__ lookup,
    const float* __restrict__ Wv)
{
    __shared__ float sm[256];
    int blk = blockIdx.x, t = threadIdx.x;

    if (blk < 128) {
        // ---- conv1: block -> (b, oc); thread -> pixel. k4 s2 p1 relu ----
        int b = blk >> 5, oc = blk & 31;
        if (t < 48) sm[t] = w1[oc * 48 + t];
        __syncthreads();

        int oh = t >> 4, ow = t & 15;
        int iw0 = ow * 2 - 1;
        float acc = b1[oc];
        #pragma unroll
        for (int ic = 0; ic < 3; ic++) {
            const float* xp  = x + (b * 3 + ic) * 1024;
            const float* swp = sm + ic * 16;
            #pragma unroll
            for (int kh = 0; kh < 4; kh++) {
                int ih = oh * 2 - 1 + kh;
                if ((unsigned)ih < 32u) {
                    const float* xr = xp + ih * 32;
                    if (iw0 >= 0)  acc += xr[iw0]     * swp[kh * 4];
                    acc += xr[iw0 + 1] * swp[kh * 4 + 1];
                    acc += xr[iw0 + 2] * swp[kh * 4 + 2];
                    if (iw0 < 29)  acc += xr[iw0 + 3] * swp[kh * 4 + 3];
                }
            }
        }
        g_z1[(b * C1 + oc) * 256 + t] = fmaxf(acc, 0.0f);
    } else {
        // ---- vmat: block v handles lookup rows 4v..4v+3 ----
        int v = blk - 128;
        sm[t] = lookup[v * 256 + t];               // 4 rows staged
        __syncthreads();

        // lookup transpose: g_LT[k][4v+mi] = row[mi][k]
        {
            int k = t >> 2, mi = t & 3;
            g_LT[k * 512 + v * 4 + mi] = sm[mi * 64 + k];
        }

        // V = row @ Wv : thread -> (row-of-4, d)
        int d = t & 63;
        const float* row = sm + (t >> 6) * 64;
        float a0 = 0.f, a1 = 0.f, a2 = 0.f, a3 = 0.f;
        #pragma unroll
        for (int k = 0; k < 64; k += 4) {
            a0 += row[k]     * Wv[(k    ) * 64 + d];
            a1 += row[k + 1] * Wv[(k + 1) * 64 + d];
            a2 += row[k + 2] * Wv[(k + 2) * 64 + d];
            a3 += row[k + 3] * Wv[(k + 3) * 64 + d];
        }
        g_V[v * 256 + t] = (a0 + a1) + (a2 + a3);
    }
}

// ---------------------------------------------------------------------------
// K2: conv2 -> g_z2t (token-major). Block -> (b, oc-pair); 4-way ic split.
// Only 4KB of w2 per block; z1[b] (32KB) staged in smem.
// ---------------------------------------------------------------------------
__global__ void __launch_bounds__(512) k2_kernel(const float* __restrict__ w2,
                                                 const float* __restrict__ b2)
{
    __shared__ __align__(16) float sm[8704];
    int blk = blockIdx.x, t = threadIdx.x;
    int b = blk >> 5, ocp = blk & 31;

    float4* sz4 = (float4*)sm;
    const float4* z14 = (const float4*)(g_z1 + b * 8192);
    #pragma unroll
    for (int i = t; i < 2048; i += 512) sz4[i] = z14[i];
    __syncthreads();

    int seg = t & 3, pix = (t >> 2) & 63, ocl = t >> 8;
    int oc = ocp * 2 + ocl;
    int oh = pix >> 3, ow = pix & 7;
    int iw0 = ow * 2 - 1;
    const float4* W4 = (const float4*)(w2 + (oc * C1 + seg * 8) * 16);
    float acc = 0.f;
    #pragma unroll
    for (int ic = 0; ic < 8; ic++) {
        const float* zp = sm + (seg * 8 + ic) * 256;
        #pragma unroll
        for (int kh = 0; kh < 4; kh++) {
            int ih = oh * 2 - 1 + kh;
            if ((unsigned)ih < 16u) {
                float4 w = W4[ic * 4 + kh];
                const float* zr = zp + ih * 16;
                if (iw0 >= 0)  acc += zr[iw0]     * w.x;
                acc += zr[iw0 + 1] * w.y;
                acc += zr[iw0 + 2] * w.z;
                if (iw0 < 13)  acc += zr[iw0 + 3] * w.w;
            }
        }
    }
    sm[8192 + t] = acc;
    __syncthreads();
    if (t < 128) {
        int o2 = t >> 6, px = t & 63;
        int base = 8192 + o2 * 256 + px * 4;
        float v = (sm[base] + sm[base + 1]) + (sm[base + 2] + sm[base + 3])
                  + b2[ocp * 2 + o2];
        g_z2t[(b * 64 + px) * 64 + ocp * 2 + o2] = fmaxf(v, 0.0f);
    }
}

// ---------------------------------------------------------------------------
// K3: Hopfield retrieve, 2 tokens per block, 128 blocks x 512 threads.
//   scores: thread t <-> memory row t; k-loop over g_LT columns (coalesced
//           LDG, smem-broadcast token values, scores in registers, NO shfl
//           until the block reductions).
//   softmax: register max/exp/sum, two block reductions.
//   p@V: thread (g: 8 m-groups, d); V coalesced along d.
//   @Wo: as before.
// ---------------------------------------------------------------------------
__global__ void __launch_bounds__(512) k3_kernel(const float* __restrict__ Wo,
                                                 float* __restrict__ out)
{
    __shared__ __align__(16) float st[128];
    __shared__ float ss0[512], ss1[512];
    __shared__ float red[64];
    __shared__ float part[1024];    // [j][g][d]
    __shared__ float pre[128];
    __shared__ float pf[512];

    int blk = blockIdx.x, t = threadIdx.x;
    int lane = t & 31, warp = t >> 5;
    int b = blk >> 5, p0 = (blk & 31) * 2;

    if (t < 128) st[t] = g_z2t[(b * 64 + p0) * 64 + t];
    __syncthreads();

    // ---- scores for row t, both tokens, registers ----
    float a0 = 0.f, a1 = 0.f, c0 = 0.f, c1 = 0.f;
    #pragma unroll
    for (int k = 0; k < 64; k += 2) {
        float L0 = g_LT[(k    ) * 512 + t];
        float L1 = g_LT[(k + 1) * 512 + t];
        a0 += L0 * st[k];        c0 += L0 * st[64 + k];
        a1 += L1 * st[k + 1];    c1 += L1 * st[64 + k + 1];
    }
    float s0 = (a0 + a1) * 0.125f;   // 1/sqrt(64)
    float s1 = (c0 + c1) * 0.125f;

    // ---- block max (dual) ----
    float mx0 = s0, mx1 = s1;
    #pragma unroll
    for (int o = 16; o; o >>= 1) {
        mx0 = fmaxf(mx0, __shfl_xor_sync(0xffffffffu, mx0, o));
        mx1 = fmaxf(mx1, __shfl_xor_sync(0xffffffffu, mx1, o));
    }
    if (lane == 0) { red[warp] = mx0; red[16 + warp] = mx1; }
    __syncthreads();
    mx0 = red[0]; mx1 = red[16];
    #pragma unroll
    for (int i = 1; i < 16; i++) {
        mx0 = fmaxf(mx0, red[i]); mx1 = fmaxf(mx1, red[16 + i]);
    }

    // ---- exp + block sum (dual) ----
    float e0 = __expf(s0 - mx0), e1 = __expf(s1 - mx1);
    ss0[t] = e0; ss1[t] = e1;
    float u0 = e0, u1 = e1;
    #pragma unroll
    for (int o = 16; o; o >>= 1) {
        u0 += __shfl_xor_sync(0xffffffffu, u0, o);
        u1 += __shfl_xor_sync(0xffffffffu, u1, o);
    }
    if (lane == 0) { red[32 + warp] = u0; red[48 + warp] = u1; }
    __syncthreads();                 // covers ss writes + red
    float tot0 = red[32], tot1 = red[48];
    #pragma unroll
    for (int i = 1; i < 16; i++) { tot0 += red[32 + i]; tot1 += red[48 + i]; }
    float inv0 = __frcp_rn(tot0), inv1 = __frcp_rn(tot1);

    // ---- p@V: thread (g = t>>6 in 0..7, d = t&63); 64 m-rows per group ----
    {
        int g = t >> 6, d = t & 63;
        const float* Vp = g_V + g * 64 * 64 + d;
        const float* q0 = ss0 + g * 64;
        const float* q1 = ss1 + g * 64;
        float A0 = 0.f, A1 = 0.f, B0 = 0.f, B1 = 0.f;
        #pragma unroll
        for (int m = 0; m < 64; m += 2) {
            float v0 = Vp[m * 64];
            float v1 = Vp[(m + 1) * 64];
            A0 += q0[m] * v0;      B0 += q1[m] * v0;
            A1 += q0[m + 1] * v1;  B1 += q1[m + 1] * v1;
        }
        part[g * 64 + d]       = A0 + A1;
        part[512 + g * 64 + d] = B0 + B1;
    }
    __syncthreads();
    if (t < 128) {
        int j = t >> 6, d = t & 63;
        const float* pp = part + j * 512;
        float s = (pp[d] + pp[64 + d]) + (pp[128 + d] + pp[192 + d])
                + (pp[256 + d] + pp[320 + d]) + (pp[384 + d] + pp[448 + d]);
        pre[j * 64 + d] = s * (j ? inv1 : inv0);
    }
    __syncthreads();

    // ---- @Wo: thread (h4 = t>>7, j = (t>>6)&1, e = t&63) ----
    {
        int e = t & 63, j = (t >> 6) & 1, h4 = t >> 7;
        const float* pj = pre + j * 64;
        float acc = 0.f;
        int d0 = h4 * 16;
        #pragma unroll
        for (int d = d0; d < d0 + 16; d++) acc += pj[d] * Wo[d * 64 + e];
        pf[t] = acc;
    }
    __syncthreads();
    if (t < 128) {
        int j = t >> 6, e = t & 63;
        out[b * 4096 + e * 64 + p0 + j] =
            (pf[t] + pf[t + 128]) + (pf[t + 256] + pf[t + 384]);
    }
}

// ---------------------------------------------------------------------------
extern "C" void kernel_launch(void* const* d_in, const int* in_sizes, int n_in,
                              void* d_out, int out_size) {
    const float* x       = (const float*)d_in[0];
    const float* conv1_w = (const float*)d_in[1];
    const float* conv1_b = (const float*)d_in[2];
    const float* conv2_w = (const float*)d_in[3];
    const float* conv2_b = (const float*)d_in[4];
    const float* lookup  = (const float*)d_in[5];
    const float* Wv      = (const float*)d_in[6];
    const float* Wo      = (const float*)d_in[7];
    float* out = (float*)d_out;

    k1_kernel<<<256, 256>>>(x, conv1_w, conv1_b, lookup, Wv);
    k2_kernel<<<128, 512>>>(conv2_w, conv2_b);
    k3_kernel<<<128, 512>>>(Wo, out);
}

// round 6
// speedup vs baseline: 1.1634x; 1.1634x over previous
#include <cuda_runtime.h>

#define BATCH 4
#define C1    32
#define C2    64
#define MROWS 512
#define NB    128
#define NT    512

// Intermediates (no allocation allowed -> __device__ globals)
__device__ float g_z1[BATCH * C1 * 256];          // conv1 out: [b][ic][16x16]
__device__ __align__(16) float g_V [MROWS * C2];  // lookup @ Wv       [m][d]
__device__ float g_LT[C2 * MROWS];                // lookup transposed [k][m]
__device__ unsigned g_bar;                        // monotonic grid-barrier ticket

// Software grid barrier: valid because all NB blocks are co-resident
// (128 blocks <= 148 SMs, 512 thr, ~12KB smem). Monotonic counter -> safe
// across graph replays with no reset.
__device__ __forceinline__ void gridbar() {
    __threadfence();
    __syncthreads();
    if (threadIdx.x == 0) {
        unsigned ticket = atomicAdd(&g_bar, 1u);
        unsigned target = (ticket / NB + 1u) * NB;
        while (*(volatile unsigned*)&g_bar < target) { }
        __threadfence();
    }
    __syncthreads();
}

__global__ void __launch_bounds__(NT) fused_kernel(
    const float* __restrict__ x,  const float* __restrict__ w1, const float* __restrict__ b1,
    const float* __restrict__ w2, const float* __restrict__ b2,
    const float* __restrict__ lookup, const float* __restrict__ Wv,
    const float* __restrict__ Wo, float* __restrict__ out)
{
    __shared__ __align__(16) float sm[2880];   // 11.5 KB, reused per phase
    // Phase C layout (st written at end of phase B, persists through C):
    float* st   = sm;          // 128: the 2 token vectors [pix][oc]
    float* ss0  = sm + 128;    // 512
    float* ss1  = sm + 640;    // 512
    float* red  = sm + 1152;   // 64
    float* part = sm + 1216;   // 1024
    float* pre  = sm + 2240;   // 128
    float* pf   = sm + 2368;   // 512
    // Phase B scratch (disjoint from st):
    float* sz    = sm + 1216;  // 1024: z1 patch [ic][kh4][8pad]
    float* zpart = sm + 128;   // 512

    int t    = threadIdx.x;
    int blk  = blockIdx.x;
    int lane = t & 31, warp = t >> 5;

    // ============ Phase A: conv1 (t<256) || vmat + LT (t>=256) ==============
    // stage: conv1 weights for (blk&31) oc  +  this block's 4 lookup rows
    if (t < 48)   sm[t] = w1[(blk & 31) * 48 + t];
    if (t >= 256) sm[64 + (t - 256)] = lookup[blk * 256 + (t - 256)];
    __syncthreads();

    if (t < 256) {
        // conv1: block -> (b, oc); thread -> output pixel. k4 s2 p1 relu.
        int b = blk >> 5, oc = blk & 31;
        int oh = t >> 4, ow = t & 15;
        int iw0 = ow * 2 - 1;
        float acc = b1[oc];
        #pragma unroll
        for (int ic = 0; ic < 3; ic++) {
            const float* xp  = x + (b * 3 + ic) * 1024;
            const float* swp = sm + ic * 16;
            #pragma unroll
            for (int kh = 0; kh < 4; kh++) {
                int ih = oh * 2 - 1 + kh;
                if ((unsigned)ih < 32u) {
                    const float* xr = xp + ih * 32;
                    if (iw0 >= 0)  acc += xr[iw0]     * swp[kh * 4];
                    acc += xr[iw0 + 1] * swp[kh * 4 + 1];
                    acc += xr[iw0 + 2] * swp[kh * 4 + 2];
                    if (iw0 < 29)  acc += xr[iw0 + 3] * swp[kh * 4 + 3];
                }
            }
        }
        g_z1[(b * C1 + oc) * 256 + t] = fmaxf(acc, 0.0f);
    } else {
        int i = t - 256;                              // 0..255
        // lookup transpose: g_LT[k][4*blk+mi] = row[mi][k]
        {
            int k = i >> 2, mi = i & 3;
            g_LT[k * 512 + blk * 4 + mi] = sm[64 + mi * 64 + k];
        }
        // vmat: V[4blk+r][d] = row_r . Wv[:,d]
        int d = i & 63;
        const float* row = sm + 64 + (i >> 6) * 64;
        float a0 = 0.f, a1 = 0.f, a2 = 0.f, a3 = 0.f;
        #pragma unroll
        for (int k = 0; k < 64; k += 4) {
            a0 += row[k]     * Wv[(k    ) * 64 + d];
            a1 += row[k + 1] * Wv[(k + 1) * 64 + d];
            a2 += row[k + 2] * Wv[(k + 2) * 64 + d];
            a3 += row[k + 3] * Wv[(k + 3) * 64 + d];
        }
        g_V[blk * 256 + i] = (a0 + a1) + (a2 + a3);
    }
    gridbar();   // the ONLY global sync

    // ============ Phase B: conv2 for this block's 2 tokens ==================
    int b = blk >> 5, p0 = (blk & 31) * 2;    // 2 adjacent pixels, same row
    {
        int oh = p0 >> 3, ow0 = p0 & 7;
        int r0 = oh * 2 - 1, c0 = ow0 * 2 - 1;

        // zero-padded z1 patch: 32 ic x 4 rows x 6 cols (stored 8-padded)
        for (int i = t; i < 1024; i += NT) {
            int ic = i >> 5, e = i & 31;
            int kh = e >> 3, kc = e & 7;
            float v = 0.0f;
            if (kc < 6) {
                int ih = r0 + kh, iw = c0 + kc;
                if ((unsigned)ih < 16u && (unsigned)iw < 16u)
                    v = g_z1[(b * C1 + ic) * 256 + ih * 16 + iw];
            }
            sz[i] = v;
        }
        __syncthreads();

        // 512 threads: pix = t&1, oc = (t>>1)&63, quarter = t>>7 (8 ic each)
        int pix = t & 1, oc = (t >> 1) & 63, qr = t >> 7;
        const float4* W4 = (const float4*)(w2 + (oc * C1 + qr * 8) * 16);
        int cb = 2 * pix;
        float acc = 0.0f;
        #pragma unroll
        for (int ic = 0; ic < 8; ic++) {
            const float* zp = sz + (qr * 8 + ic) * 32 + cb;
            float4 wa = W4[ic * 4 + 0], wb = W4[ic * 4 + 1];
            float4 wc = W4[ic * 4 + 2], wd = W4[ic * 4 + 3];
            acc += zp[0]  * wa.x + zp[1]  * wa.y + zp[2]  * wa.z + zp[3]  * wa.w;
            acc += zp[8]  * wb.x + zp[9]  * wb.y + zp[10] * wb.z + zp[11] * wb.w;
            acc += zp[16] * wc.x + zp[17] * wc.y + zp[18] * wc.z + zp[19] * wc.w;
            acc += zp[24] * wd.x + zp[25] * wd.y + zp[26] * wd.z + zp[27] * wd.w;
        }
        zpart[t] = acc;
        __syncthreads();
        if (t < 128) {
            int px = t & 1, o = t >> 1;
            float v = (zpart[t] + zpart[t + 128]) + (zpart[t + 256] + zpart[t + 384])
                      + b2[o];
            st[px * 64 + o] = fmaxf(v, 0.0f);
        }
        __syncthreads();
    }

    // ============ Phase C: Hopfield retrieve (2 tokens) =====================
    // ---- scores for memory row t, both tokens, registers, coalesced LT ----
    float a0 = 0.f, a1 = 0.f, c0s = 0.f, c1s = 0.f;
    #pragma unroll
    for (int k = 0; k < 64; k += 2) {
        float L0 = g_LT[(k    ) * 512 + t];
        float L1 = g_LT[(k + 1) * 512 + t];
        a0  += L0 * st[k];        c0s += L0 * st[64 + k];
        a1  += L1 * st[k + 1];    c1s += L1 * st[64 + k + 1];
    }
    float s0 = (a0 + a1) * 0.125f;   // 1/sqrt(64)
    float s1 = (c0s + c1s) * 0.125f;

    // ---- block max (dual) ----
    float mx0 = s0, mx1 = s1;
    #pragma unroll
    for (int o = 16; o; o >>= 1) {
        mx0 = fmaxf(mx0, __shfl_xor_sync(0xffffffffu, mx0, o));
        mx1 = fmaxf(mx1, __shfl_xor_sync(0xffffffffu, mx1, o));
    }
    if (lane == 0) { red[warp] = mx0; red[16 + warp] = mx1; }
    __syncthreads();
    mx0 = red[0]; mx1 = red[16];
    #pragma unroll
    for (int i = 1; i < 16; i++) {
        mx0 = fmaxf(mx0, red[i]); mx1 = fmaxf(mx1, red[16 + i]);
    }

    // ---- exp + block sum (dual) ----
    float e0 = __expf(s0 - mx0), e1 = __expf(s1 - mx1);
    ss0[t] = e0; ss1[t] = e1;
    float u0 = e0, u1 = e1;
    #pragma unroll
    for (int o = 16; o; o >>= 1) {
        u0 += __shfl_xor_sync(0xffffffffu, u0, o);
        u1 += __shfl_xor_sync(0xffffffffu, u1, o);
    }
    if (lane == 0) { red[32 + warp] = u0; red[48 + warp] = u1; }
    __syncthreads();                 // covers ss writes + red
    float tot0 = red[32], tot1 = red[48];
    #pragma unroll
    for (int i = 1; i < 16; i++) { tot0 += red[32 + i]; tot1 += red[48 + i]; }
    float inv0 = __frcp_rn(tot0), inv1 = __frcp_rn(tot1);

    // ---- p@V: thread (g = t>>6 in 0..7, d = t&63); V coalesced along d ----
    {
        int g = t >> 6, d = t & 63;
        const float* Vp = g_V + g * 64 * 64 + d;
        const float* q0 = ss0 + g * 64;
        const float* q1 = ss1 + g * 64;
        float A0 = 0.f, A1 = 0.f, B0 = 0.f, B1 = 0.f;
        #pragma unroll
        for (int m = 0; m < 64; m += 2) {
            float v0 = Vp[m * 64];
            float v1 = Vp[(m + 1) * 64];
            A0 += q0[m] * v0;      B0 += q1[m] * v0;
            A1 += q0[m + 1] * v1;  B1 += q1[m + 1] * v1;
        }
        part[g * 64 + d] = A0 + A1;         // token0 partials (8 groups)
        float bsum = B0 + B1;               // token1 partials -> reuse zpart? no:
        __syncthreads();                    // token0 partials ready
        if (t < 64) {
            float s = (part[t] + part[64 + t]) + (part[128 + t] + part[192 + t])
                    + (part[256 + t] + part[320 + t]) + (part[384 + t] + part[448 + t]);
            pre[t] = s * inv0;
        }
        __syncthreads();
        part[g * 64 + d] = bsum;
        __syncthreads();
        if (t < 64) {
            float s = (part[t] + part[64 + t]) + (part[128 + t] + part[192 + t])
                    + (part[256 + t] + part[320 + t]) + (part[384 + t] + part[448 + t]);
            pre[64 + t] = s * inv1;
        }
        __syncthreads();
    }

    // ---- @Wo: thread (h4 = t>>7, j = (t>>6)&1, e = t&63); Wo coalesced ----
    {
        int e = t & 63, j = (t >> 6) & 1, h4 = t >> 7;
        const float* pj = pre + j * 64;
        float acc = 0.f;
        int d0 = h4 * 16;
        #pragma unroll
        for (int d = d0; d < d0 + 16; d++) acc += pj[d] * Wo[d * 64 + e];
        pf[t] = acc;
    }
    __syncthreads();
    if (t < 128) {
        int j = t >> 6, e = t & 63;
        out[b * 4096 + e * 64 + p0 + j] =
            (pf[t] + pf[t + 128]) + (pf[t + 256] + pf[t + 384]);
    }
}

// ---------------------------------------------------------------------------
extern "C" void kernel_launch(void* const* d_in, const int* in_sizes, int n_in,
                              void* d_out, int out_size) {
    const float* x       = (const float*)d_in[0];
    const float* conv1_w = (const float*)d_in[1];
    const float* conv1_b = (const float*)d_in[2];
    const float* conv2_w = (const float*)d_in[3];
    const float* conv2_b = (const float*)d_in[4];
    const float* lookup  = (const float*)d_in[5];
    const float* Wv      = (const float*)d_in[6];
    const float* Wo      = (const float*)d_in[7];
    float* out = (float*)d_out;

    fused_kernel<<<NB, NT>>>(x, conv1_w, conv1_b, conv2_w, conv2_b,
                             lookup, Wv, Wo, out);
}